// round 16
// baseline (speedup 1.0000x reference)
#include <cuda_runtime.h>

#define B_    16
#define C_    64
#define COUT_ 64
#define L_    16384
#define K_    3
#define CK_   (K_ * C_)   // 192
#define TLB_  64          // l per block (offmsk kernel)
#define TL_   64          // l per block (main kernel)
#define OSTR_ 66          // output staging stride
#define NT_   256

// scratch (no allocations allowed)
__device__ float g_wtd[CK_ * COUT_ * 2];  // [ck][2o]: (w,w) duplicated pairs
__device__ float g_off[B_ * K_ * L_];     // [b][k][l]
__device__ float g_msk[B_ * K_ * L_];     // [b][k][l]

// ---------------- f32x2 helpers ----------------
__device__ __forceinline__ void unpack2(unsigned long long v, float& lo, float& hi) {
    asm("mov.b64 {%0, %1}, %2;" : "=f"(lo), "=f"(hi) : "l"(v));
}
__device__ __forceinline__ void fma2(unsigned long long& d, unsigned long long a,
                                     unsigned long long b) {
    asm("fma.rn.f32x2 %0, %1, %2, %0;" : "+l"(d) : "l"(a), "l"(b));
}

// ================= kernel A: weight transpose + duplicate =================
// weight[o][c][k] -> g_wtd[(k*64+c)*128 + 2o {,+1}] = w
__global__ void wt_kernel(const float* __restrict__ weight) {
    int i = blockIdx.x * blockDim.x + threadIdx.x;
    if (i < CK_ * COUT_) {
        int o  = i & 63;
        int ck = i >> 6;
        int c  = ck & 63;
        int k  = ck >> 6;
        float w = weight[o * CK_ + c * K_ + k];
        g_wtd[ck * 128 + 2 * o]     = w;
        g_wtd[ck * 128 + 2 * o + 1] = w;
    }
}

// ================= kernel B: offset / mask branches =================
// dynamic smem: 8192 floats (32 KB): dwAT [c][li], dwBT [c][li]
__global__ __launch_bounds__(NT_, 4) void offmsk_kernel(
    const float* __restrict__ x,
    const float* __restrict__ wodw, const float* __restrict__ bodw,
    const float* __restrict__ wopw, const float* __restrict__ bopw,
    const float* __restrict__ wmdw, const float* __restrict__ bmdw,
    const float* __restrict__ wmpw, const float* __restrict__ bmpw)
{
    extern __shared__ float smem[];
    float* dwAT = smem;           // 4096  [c][li]
    float* dwBT = smem + 4096;    // 4096  [c][li]

    __shared__ float s_wdwA[448], s_wdwB[448];
    __shared__ float s_bdwA[64],  s_bdwB[64];
    __shared__ float s_wpwA[192], s_wpwB[192];
    __shared__ float s_bpwA[4],   s_bpwB[4];

    const int tid = threadIdx.x;
    const int b   = blockIdx.y;
    const int l0  = blockIdx.x * TLB_;
    const float* xb = x + (long)b * 64 * L_;

    #pragma unroll
    for (int i = tid; i < 448; i += NT_) { s_wdwA[i] = wodw[i]; s_wdwB[i] = wmdw[i]; }
    if (tid < 64)  { s_bdwA[tid] = bodw[tid]; s_bdwB[tid] = bmdw[tid]; }
    if (tid < 192) { s_wpwA[tid] = wopw[tid]; s_wpwB[tid] = wmpw[tid]; }
    if (tid < 3)   { s_bpwA[tid] = bopw[tid]; s_bpwB[tid] = bmpw[tid]; }
    __syncthreads();

    // depthwise 7-tap conv, register-blocked (x read once)
    {
        const int lg    = tid & 15;
        const int c0    = tid >> 4;
        const int lbase = lg * 4;
        const bool safe = (l0 + lbase - 4 >= 0) && (l0 + lbase + 8 <= L_);
        #pragma unroll
        for (int it = 0; it < 4; ++it) {
            int c = it * 16 + c0;
            const float* xr = xb + c * L_;
            float xw[12];
            if (safe) {
                const float4* x4 = (const float4*)(xr + l0 + lbase - 4);
                float4 f0 = x4[0], f1 = x4[1], f2 = x4[2];
                xw[0]=f0.x; xw[1]=f0.y; xw[2]=f0.z; xw[3]=f0.w;
                xw[4]=f1.x; xw[5]=f1.y; xw[6]=f1.z; xw[7]=f1.w;
                xw[8]=f2.x; xw[9]=f2.y; xw[10]=f2.z; xw[11]=f2.w;
            } else {
                #pragma unroll
                for (int j = 0; j < 12; ++j) {
                    int idx = l0 + lbase - 4 + j;
                    xw[j] = (idx >= 0 && idx < L_) ? xr[idx] : 0.f;
                }
            }
            float4 rA, rB;
            float* pA = (float*)&rA;
            float* pB = (float*)&rB;
            #pragma unroll
            for (int i = 0; i < 4; ++i) {
                float sA = s_bdwA[c], sB = s_bdwB[c];
                #pragma unroll
                for (int t = 0; t < 7; ++t) {
                    float xv = xw[i + t + 1];
                    sA = fmaf(xv, s_wdwA[c * 7 + t], sA);
                    sB = fmaf(xv, s_wdwB[c * 7 + t], sB);
                }
                pA[i] = sA; pB[i] = sB;
            }
            *(float4*)(dwAT + c * 64 + lbase) = rA;
            *(float4*)(dwBT + c * 64 + lbase) = rB;
        }
    }
    __syncthreads();

    // 1x1 conv -> off/msk, coalesced global write [b][k][l]
    if (tid < 192) {
        const int li = tid & 63;
        const int k  = tid >> 6;
        float oA = s_bpwA[k], oB = s_bpwB[k];
        const float* wA = s_wpwA + k * 64;
        const float* wB = s_wpwB + k * 64;
        #pragma unroll 8
        for (int c = 0; c < 64; ++c) {
            oA = fmaf(dwAT[c * 64 + li], wA[c], oA);
            oB = fmaf(dwBT[c * 64 + li], wB[c], oB);
        }
        long gi = ((long)(b * 3 + k)) * L_ + l0 + li;
        g_off[gi] = oA;
        g_msk[gi] = 1.f / (1.f + __expf(-oB));
    }
}

// ================= main kernel: gather + GEMM, 4 blocks/SM =================
// dynamic smem: 12288 floats (49152 B) — xv_s [ck][li]; out_s overlays at end
__global__ __launch_bounds__(NT_, 4) void main_kernel(
    const float* __restrict__ x,
    const float* __restrict__ bias,
    float* __restrict__ out)
{
    extern __shared__ float smem[];
    float* xv_s = smem;            // 12288 floats

    __shared__ float bias_s[64];

    const int tid = threadIdx.x;
    const int b   = blockIdx.y;
    const int l0  = blockIdx.x * TL_;
    const float* xb = x + (long)b * 64 * L_;

    if (tid < 64) bias_s[tid] = bias[tid];

    // ---- gather + interp -> xv_s[ck][li]; off/msk hoisted to registers ----
    {
        const int li  = tid & 63;
        const int ck0 = tid >> 6;     // 0..3
        const float* offp = g_off + (long)b * 3 * L_ + l0 + li;
        const float* mskp = g_msk + (long)b * 3 * L_ + l0 + li;
        float offr0 = __ldg(offp);          float mskr0 = __ldg(mskp);
        float offr1 = __ldg(offp + L_);     float mskr1 = __ldg(mskp + L_);
        float offr2 = __ldg(offp + 2 * L_); float mskr2 = __ldg(mskp + 2 * L_);

        #pragma unroll
        for (int k = 0; k < 3; ++k) {
            float off = (k == 0) ? offr0 : (k == 1) ? offr1 : offr2;
            float m   = (k == 0) ? mskr0 : (k == 1) ? mskr1 : mskr2;
            float p  = (float)(l0 + li - 1 + k) + off;
            float fi = floorf(p);
            float f  = p - fi;
            int i0 = (int)fi;
            int i1 = i0 + 1;
            float f0 = 1.f - f;
            #pragma unroll 4
            for (int it = 0; it < 16; ++it) {
                int c  = it * 4 + ck0;
                const float* xr = xb + c * L_;
                float x0 = (i0 >= 0 && i0 < L_) ? __ldg(xr + i0) : 0.f;
                float x1 = (i1 >= 0 && i1 < L_) ? __ldg(xr + i1) : 0.f;
                xv_s[(k * 64 + c) * 64 + li] = (f0 * x0 + f * x1) * m;
            }
        }
    }
    __syncthreads();

    // ---- GEMM: out[o][l] = sum_ck w[ck][o] * xv[ck][l] ----
    // square warp tile 32o x 16l; thread 4o x 4l
    // w = pre-duplicated (w,w) pairs via 2 LDG.128; x = native l-pairs 1 LDS.128
    // -> ZERO MOVs in inner loop
    const int warp  = tid >> 5;
    const int lane  = tid & 31;
    const int obase = (warp & 1) * 32 + (lane & 7) * 4;
    const int lbase = (warp >> 1) * 16 + (lane >> 3) * 4;

    unsigned long long acc[8];    // [oo*2 + lp]
    #pragma unroll
    for (int i = 0; i < 8; ++i) acc[i] = 0ULL;

    const unsigned long long* wp =
        (const unsigned long long*)(g_wtd + 2 * obase);
    const float* xp = xv_s + lbase;

    #pragma unroll 4
    for (int ck = 0; ck < CK_; ++ck) {
        ulonglong2 wd01 = __ldg((const ulonglong2*)wp);        // (w0,w0),(w1,w1)
        ulonglong2 wd23 = __ldg((const ulonglong2*)(wp + 2));  // (w2,w2),(w3,w3)
        wp += 64;                                              // 128 floats
        ulonglong2 xu = *(const ulonglong2*)xp;    xp += 64;   // (l0,l1),(l2,l3)
        fma2(acc[0], wd01.x, xu.x); fma2(acc[1], wd01.x, xu.y);
        fma2(acc[2], wd01.y, xu.x); fma2(acc[3], wd01.y, xu.y);
        fma2(acc[4], wd23.x, xu.x); fma2(acc[5], wd23.x, xu.y);
        fma2(acc[6], wd23.y, xu.x); fma2(acc[7], wd23.y, xu.y);
    }
    __syncthreads();

    // ---- stage [o][l] + coalesced store ----
    float* out_s = smem;   // [o][l] stride OSTR_ (xv region dead)
    #pragma unroll
    for (int oo = 0; oo < 4; ++oo) {
        #pragma unroll
        for (int lp = 0; lp < 2; ++lp) {
            float lo, hi;
            unpack2(acc[oo * 2 + lp], lo, hi);
            *(float2*)&out_s[(obase + oo) * OSTR_ + lbase + lp * 2] =
                make_float2(lo, hi);
        }
    }
    __syncthreads();

    {
        const int l  = tid & 63;
        const int o0 = tid >> 6;
        #pragma unroll
        for (int it = 0; it < 16; ++it) {
            int o = it * 4 + o0;
            out[((long)(b * 64 + o)) * L_ + l0 + l] = out_s[o * OSTR_ + l] + bias_s[o];
        }
    }
}

// ================= host =================
extern "C" void kernel_launch(void* const* d_in, const int* in_sizes, int n_in,
                              void* d_out, int out_size) {
    const float* x      = (const float*)d_in[0];
    const float* wodw   = (const float*)d_in[1];
    const float* bodw   = (const float*)d_in[2];
    const float* wopw   = (const float*)d_in[3];
    const float* bopw   = (const float*)d_in[4];
    const float* wmdw   = (const float*)d_in[5];
    const float* bmdw   = (const float*)d_in[6];
    const float* wmpw   = (const float*)d_in[7];
    const float* bmpw   = (const float*)d_in[8];
    const float* weight = (const float*)d_in[9];
    const float* bias   = (const float*)d_in[10];
    float* out = (float*)d_out;

    wt_kernel<<<(CK_ * COUT_ + 255) / 256, 256>>>(weight);

    dim3 gridB(L_ / TLB_, B_);
    const int smem_b = 8192 * (int)sizeof(float);   // 32768 B
    cudaFuncSetAttribute(offmsk_kernel, cudaFuncAttributeMaxDynamicSharedMemorySize, smem_b);
    offmsk_kernel<<<gridB, NT_, smem_b>>>(x, wodw, bodw, wopw, bopw,
                                          wmdw, bmdw, wmpw, bmpw);

    dim3 gridM(L_ / TL_, B_);
    const int smem_m = 12288 * (int)sizeof(float);  // 49152 B
    cudaFuncSetAttribute(main_kernel, cudaFuncAttributeMaxDynamicSharedMemorySize, smem_m);
    main_kernel<<<gridM, NT_, smem_m>>>(x, bias, out);
}

// round 17
// speedup vs baseline: 2.0598x; 2.0598x over previous
#include <cuda_runtime.h>

#define B_    16
#define C_    64
#define COUT_ 64
#define L_    16384
#define K_    3
#define CK_   (K_ * C_)   // 192
#define TLB_  64          // l per block (offmsk kernel)
#define TL_   64          // l per block (main kernel)
#define OSTR_ 66          // output staging stride
#define NT_   256

// scratch (no allocations allowed)
__device__ float g_wt[CK_ * COUT_];       // [ck][o], ck = k*64 + c
__device__ float g_off[B_ * K_ * L_];     // [b][k][l]
__device__ float g_msk[B_ * K_ * L_];     // [b][k][l]

// ---------------- f32x2 helpers ----------------
__device__ __forceinline__ unsigned long long pack2(float lo, float hi) {
    unsigned long long r;
    asm("mov.b64 %0, {%1, %2};" : "=l"(r) : "f"(lo), "f"(hi));
    return r;
}
__device__ __forceinline__ void unpack2(unsigned long long v, float& lo, float& hi) {
    asm("mov.b64 {%0, %1}, %2;" : "=f"(lo), "=f"(hi) : "l"(v));
}
__device__ __forceinline__ void fma2(unsigned long long& d, unsigned long long a,
                                     unsigned long long b) {
    asm("fma.rn.f32x2 %0, %1, %2, %0;" : "+l"(d) : "l"(a), "l"(b));
}

// ================= kernel A: weight transpose =================
__global__ void wt_kernel(const float* __restrict__ weight) {
    int i = blockIdx.x * blockDim.x + threadIdx.x;
    if (i < CK_ * COUT_) {
        int o  = i & 63;
        int ck = i >> 6;
        int c  = ck & 63;
        int k  = ck >> 6;
        g_wt[i] = weight[o * CK_ + c * K_ + k];
    }
}

// ================= kernel B: offset / mask branches =================
// dynamic smem: 8192 floats (32 KB): dwAT [c][li], dwBT [c][li]
__global__ __launch_bounds__(NT_, 4) void offmsk_kernel(
    const float* __restrict__ x,
    const float* __restrict__ wodw, const float* __restrict__ bodw,
    const float* __restrict__ wopw, const float* __restrict__ bopw,
    const float* __restrict__ wmdw, const float* __restrict__ bmdw,
    const float* __restrict__ wmpw, const float* __restrict__ bmpw)
{
    extern __shared__ float smem[];
    float* dwAT = smem;           // 4096  [c][li]
    float* dwBT = smem + 4096;    // 4096  [c][li]

    __shared__ float s_wdwA[448], s_wdwB[448];
    __shared__ float s_bdwA[64],  s_bdwB[64];
    __shared__ float s_wpwA[192], s_wpwB[192];
    __shared__ float s_bpwA[4],   s_bpwB[4];

    const int tid = threadIdx.x;
    const int b   = blockIdx.y;
    const int l0  = blockIdx.x * TLB_;
    const float* xb = x + (long)b * 64 * L_;

    #pragma unroll
    for (int i = tid; i < 448; i += NT_) { s_wdwA[i] = wodw[i]; s_wdwB[i] = wmdw[i]; }
    if (tid < 64)  { s_bdwA[tid] = bodw[tid]; s_bdwB[tid] = bmdw[tid]; }
    if (tid < 192) { s_wpwA[tid] = wopw[tid]; s_wpwB[tid] = wmpw[tid]; }
    if (tid < 3)   { s_bpwA[tid] = bopw[tid]; s_bpwB[tid] = bmpw[tid]; }
    __syncthreads();

    // depthwise 7-tap conv, register-blocked (x read once)
    {
        const int lg    = tid & 15;
        const int c0    = tid >> 4;
        const int lbase = lg * 4;
        const bool safe = (l0 + lbase - 4 >= 0) && (l0 + lbase + 8 <= L_);
        #pragma unroll
        for (int it = 0; it < 4; ++it) {
            int c = it * 16 + c0;
            const float* xr = xb + c * L_;
            float xw[12];
            if (safe) {
                const float4* x4 = (const float4*)(xr + l0 + lbase - 4);
                float4 f0 = x4[0], f1 = x4[1], f2 = x4[2];
                xw[0]=f0.x; xw[1]=f0.y; xw[2]=f0.z; xw[3]=f0.w;
                xw[4]=f1.x; xw[5]=f1.y; xw[6]=f1.z; xw[7]=f1.w;
                xw[8]=f2.x; xw[9]=f2.y; xw[10]=f2.z; xw[11]=f2.w;
            } else {
                #pragma unroll
                for (int j = 0; j < 12; ++j) {
                    int idx = l0 + lbase - 4 + j;
                    xw[j] = (idx >= 0 && idx < L_) ? xr[idx] : 0.f;
                }
            }
            float4 rA, rB;
            float* pA = (float*)&rA;
            float* pB = (float*)&rB;
            #pragma unroll
            for (int i = 0; i < 4; ++i) {
                float sA = s_bdwA[c], sB = s_bdwB[c];
                #pragma unroll
                for (int t = 0; t < 7; ++t) {
                    float xv = xw[i + t + 1];
                    sA = fmaf(xv, s_wdwA[c * 7 + t], sA);
                    sB = fmaf(xv, s_wdwB[c * 7 + t], sB);
                }
                pA[i] = sA; pB[i] = sB;
            }
            *(float4*)(dwAT + c * 64 + lbase) = rA;
            *(float4*)(dwBT + c * 64 + lbase) = rB;
        }
    }
    __syncthreads();

    // 1x1 conv -> off/msk, coalesced global write [b][k][l]
    if (tid < 192) {
        const int li = tid & 63;
        const int k  = tid >> 6;
        float oA = s_bpwA[k], oB = s_bpwB[k];
        const float* wA = s_wpwA + k * 64;
        const float* wB = s_wpwB + k * 64;
        #pragma unroll 8
        for (int c = 0; c < 64; ++c) {
            oA = fmaf(dwAT[c * 64 + li], wA[c], oA);
            oB = fmaf(dwBT[c * 64 + li], wB[c], oB);
        }
        long gi = ((long)(b * 3 + k)) * L_ + l0 + li;
        g_off[gi] = oA;
        g_msk[gi] = 1.f / (1.f + __expf(-oB));
    }
}

// ================= main kernel: gather + GEMM, 4 blocks/SM =================
// dynamic smem: 12288 floats (49152 B) — xv_s [ck][li]; out_s overlays at end
__global__ __launch_bounds__(NT_, 4) void main_kernel(
    const float* __restrict__ x,
    const float* __restrict__ bias,
    float* __restrict__ out)
{
    extern __shared__ float smem[];
    float* xv_s = smem;            // 12288 floats

    __shared__ float bias_s[64];

    const int tid = threadIdx.x;
    const int b   = blockIdx.y;
    const int l0  = blockIdx.x * TL_;
    const float* xb = x + (long)b * 64 * L_;

    if (tid < 64) bias_s[tid] = bias[tid];

    // ---- gather + interp -> xv_s[ck][li]; off/msk + positions hoisted ----
    {
        const int li  = tid & 63;
        const int ck0 = tid >> 6;     // 0..3
        const float* offp = g_off + (long)b * 3 * L_ + l0 + li;
        const float* mskp = g_msk + (long)b * 3 * L_ + l0 + li;
        float offr0 = __ldg(offp);          float mskr0 = __ldg(mskp);
        float offr1 = __ldg(offp + L_);     float mskr1 = __ldg(mskp + L_);
        float offr2 = __ldg(offp + 2 * L_); float mskr2 = __ldg(mskp + 2 * L_);

        #pragma unroll
        for (int k = 0; k < 3; ++k) {
            float off = (k == 0) ? offr0 : (k == 1) ? offr1 : offr2;
            float m   = (k == 0) ? mskr0 : (k == 1) ? mskr1 : mskr2;
            float p  = (float)(l0 + li - 1 + k) + off;
            float fi = floorf(p);
            float f  = p - fi;
            int i0 = (int)fi;
            int i1 = i0 + 1;
            float f0 = 1.f - f;
            bool v0 = (i0 >= 0) && (i0 < L_);
            bool v1 = (i1 >= 0) && (i1 < L_);
            #pragma unroll 4
            for (int it = 0; it < 16; ++it) {
                int c  = it * 4 + ck0;
                const float* xr = xb + c * L_;
                float x0 = v0 ? __ldg(xr + i0) : 0.f;
                float x1 = v1 ? __ldg(xr + i1) : 0.f;
                xv_s[(k * 64 + c) * 64 + li] = (f0 * x0 + f * x1) * m;
            }
        }
    }
    __syncthreads();

    // ---- GEMM: out[o][l] = sum_ck w[ck][o] * xv[ck][l] ----
    // square warp tile 32o x 16l; thread 4o x 4l; w via __ldg (R14 path)
    const int warp  = tid >> 5;
    const int lane  = tid & 31;
    const int obase = (warp & 1) * 32 + (lane & 7) * 4;
    const int lbase = (warp >> 1) * 16 + (lane >> 3) * 4;

    unsigned long long acc[8];    // [oo*2 + lp]
    #pragma unroll
    for (int i = 0; i < 8; ++i) acc[i] = 0ULL;

    const float* wp = g_wt + obase;
    const float* xp = xv_s + lbase;

    #pragma unroll 4
    for (int ck = 0; ck < CK_; ++ck) {
        float4 wv = __ldg((const float4*)wp);      wp += 64;
        ulonglong2 xu = *(const ulonglong2*)xp;    xp += 64;
        unsigned long long w0 = pack2(wv.x, wv.x);
        unsigned long long w1 = pack2(wv.y, wv.y);
        unsigned long long w2 = pack2(wv.z, wv.z);
        unsigned long long w3 = pack2(wv.w, wv.w);
        fma2(acc[0], w0, xu.x); fma2(acc[1], w0, xu.y);
        fma2(acc[2], w1, xu.x); fma2(acc[3], w1, xu.y);
        fma2(acc[4], w2, xu.x); fma2(acc[5], w2, xu.y);
        fma2(acc[6], w3, xu.x); fma2(acc[7], w3, xu.y);
    }
    __syncthreads();

    // ---- stage [o][l] + coalesced store ----
    float* out_s = smem;   // [o][l] stride OSTR_ (xv region dead)
    #pragma unroll
    for (int oo = 0; oo < 4; ++oo) {
        #pragma unroll
        for (int lp = 0; lp < 2; ++lp) {
            float lo, hi;
            unpack2(acc[oo * 2 + lp], lo, hi);
            *(float2*)&out_s[(obase + oo) * OSTR_ + lbase + lp * 2] =
                make_float2(lo, hi);
        }
    }
    __syncthreads();

    {
        const int l  = tid & 63;
        const int o0 = tid >> 6;
        #pragma unroll
        for (int it = 0; it < 16; ++it) {
            int o = it * 4 + o0;
            out[((long)(b * 64 + o)) * L_ + l0 + l] = out_s[o * OSTR_ + l] + bias_s[o];
        }
    }
}

// ================= host =================
extern "C" void kernel_launch(void* const* d_in, const int* in_sizes, int n_in,
                              void* d_out, int out_size) {
    const float* x      = (const float*)d_in[0];
    const float* wodw   = (const float*)d_in[1];
    const float* bodw   = (const float*)d_in[2];
    const float* wopw   = (const float*)d_in[3];
    const float* bopw   = (const float*)d_in[4];
    const float* wmdw   = (const float*)d_in[5];
    const float* bmdw   = (const float*)d_in[6];
    const float* wmpw   = (const float*)d_in[7];
    const float* bmpw   = (const float*)d_in[8];
    const float* weight = (const float*)d_in[9];
    const float* bias   = (const float*)d_in[10];
    float* out = (float*)d_out;

    wt_kernel<<<(CK_ * COUT_ + 255) / 256, 256>>>(weight);

    dim3 gridB(L_ / TLB_, B_);
    const int smem_b = 8192 * (int)sizeof(float);   // 32768 B
    cudaFuncSetAttribute(offmsk_kernel, cudaFuncAttributeMaxDynamicSharedMemorySize, smem_b);
    offmsk_kernel<<<gridB, NT_, smem_b>>>(x, wodw, bodw, wopw, bopw,
                                          wmdw, bmdw, wmpw, bmpw);

    dim3 gridM(L_ / TL_, B_);
    const int smem_m = 12288 * (int)sizeof(float);  // 49152 B
    cudaFuncSetAttribute(main_kernel, cudaFuncAttributeMaxDynamicSharedMemorySize, smem_m);
    main_kernel<<<gridM, NT_, smem_m>>>(x, bias, out);
}